// round 9
// baseline (speedup 1.0000x reference)
#include <cuda_runtime.h>
#include <math.h>
#include <stdint.h>

typedef unsigned long long ull;

// Problem constants
#define BB 16
#define SS 1024
#define EE 300
#define HH 128
#define NHEAD 4
#define H2D 256
#define G3 384
#define NW 768
#define NOUT 3

// ---------------- device scratch (static globals: allocation-free) -----------
__device__ float g_gx_f[BB * SS * G3];
__device__ float g_gx_b[BB * SS * G3];
__device__ float g_wt[EE * NW];                    // [k][n] combined input weights
__device__ float g_rh[BB * SS * H2D];              // fwd 0:128, bwd 128:256
__device__ float g_q[BB * NHEAD * SS * H2D];       // 67 MB
__device__ float g_alpha[(size_t)BB * NHEAD * SS * SS];  // 268 MB scores scratch
__device__ float g_vp0[BB * SS];
__device__ float g_vp1[BB * SS];
__device__ float g_vp2[BB * SS];
__device__ float g_bias[BB * SS];                  // additive key mask bias
__device__ float g_const[NOUT];
__device__ int   g_is64;

// ---------------- f32x2 packed helpers ---------------------------------------
__device__ __forceinline__ void ffma2(ull& c, ull a, ull b) {
    asm("fma.rn.f32x2 %0, %1, %2, %0;" : "+l"(c) : "l"(a), "l"(b));
}
__device__ __forceinline__ ull f2pack(float lo, float hi) {
    ull u;
    asm("mov.b64 %0, {%1,%2};" : "=l"(u) : "f"(lo), "f"(hi));
    return u;
}
__device__ __forceinline__ void f2unpack(ull u, float& lo, float& hi) {
    asm("mov.b64 {%0,%1}, %2;" : "=f"(lo), "=f"(hi) : "l"(u));
}
__device__ __forceinline__ float sigmf(float x) { return 1.f / (1.f + expf(-x)); }

// ---------------- prep: transpose w_ih, dtype detect, consts -----------------
__global__ void prep_kernel(const float* __restrict__ wf, const float* __restrict__ wb,
                            const void* __restrict__ review,
                            const float* __restrict__ wrw, const float* __restrict__ wtb,
                            const float* __restrict__ wrb) {
    int idx = blockIdx.x * blockDim.x + threadIdx.x;
    if (idx == 0) {
        // int64 tokens -> odd 32-bit words all zero (tokens < 32000)
        const int* r = (const int*)review;
        int all0 = 1;
        for (int i = 1; i < 128; i += 2)
            if (r[i] != 0) all0 = 0;
        g_is64 = all0;
    }
    if (idx < NOUT) {
        float s = 0.f;
        for (int d = 0; d < H2D; d++) s += wrw[idx * H2D + d];
        g_const[idx] = wtb[0] * s + wrb[idx];
    }
    if (idx < EE * NW) {
        int k = idx / NW, n = idx % NW;
        g_wt[idx] = (n < G3) ? wf[n * EE + k] : wb[(n - G3) * EE + k];
    }
}

// ---------------- shared 128x128 fp32x2 microkernel ---------------------------
// As: [m][8] floats, k-fastest (warp-broadcast reads -> conflict-free).
// Bsu: [kp][n] ulls, each ull = packed (k=2kp, k=2kp+1) for column n.
// Thread (tx=tid&31, ty=tid>>5) owns rows ty*16..+15, cols {tx,tx+32,tx+64,tx+96}.
// LDS.64 on Bsu: lane word-addresses stride 2 -> each 16-lane phase hits all 32
// banks exactly once -> conflict-free.
__device__ __forceinline__ void mm_inner(const float (*As)[8], const ull (*Bsu)[128],
                                         int tx, int ty, ull acc[16][4]) {
    const ull* ap = (const ull*)As[ty * 16];
#pragma unroll
    for (int kp = 0; kp < 4; kp++) {
        ull b0 = Bsu[kp][tx];
        ull b1 = Bsu[kp][tx + 32];
        ull b2 = Bsu[kp][tx + 64];
        ull b3 = Bsu[kp][tx + 96];
#pragma unroll
        for (int r = 0; r < 16; r++) {
            ull a = ap[r * 4 + kp];
            ffma2(acc[r][0], a, b0);
            ffma2(acc[r][1], a, b1);
            ffma2(acc[r][2], a, b2);
            ffma2(acc[r][3], a, b3);
        }
    }
}

// Store one float of B (global [k][n] layout) into the packed smem tile.
__device__ __forceinline__ void bs_put(ull (*Bsu)[128], int kk, int n, float v) {
    ((float*)&Bsu[kk >> 1][n])[kk & 1] = v;
}

// ---------------- GEMM1: gx = emb[review] @ w_ih^T + b_ih --------------------
__global__ __launch_bounds__(256) void gemm1_kernel(const void* __restrict__ review,
                                                    const float* __restrict__ emb,
                                                    const float* __restrict__ bihf,
                                                    const float* __restrict__ bihb) {
    __shared__ __align__(16) float As[2][128][8];
    __shared__ __align__(16) ull Bsu[2][4][128];
    const int tid = threadIdx.x;
    const int m0 = blockIdx.y * 128, n0 = blockIdx.x * 128;
    const int tx = tid & 31, ty = tid >> 5;
    const int am = tid >> 1, ah = tid & 1;
    const int is64 = g_is64;
    const int tokrow = is64 ? (int)((const long long*)review)[m0 + am]
                            : ((const int*)review)[m0 + am];
    const float* arow = emb + (size_t)tokrow * EE;

    ull acc[16][4];
#pragma unroll
    for (int r = 0; r < 16; r++)
#pragma unroll
        for (int c = 0; c < 4; c++) acc[r][c] = 0ull;

    const int NK = (EE + 7) / 8;  // 38
    {   // preload tile 0
        float4 av = *(const float4*)(arow + ah * 4);
        *(float4*)&As[0][am][ah * 4] = av;
#pragma unroll
        for (int i = 0; i < 4; i++) {
            int e = tid + i * 256, kk = e >> 7, n = e & 127;
            bs_put(Bsu[0], kk, n, g_wt[(size_t)kk * NW + n0 + n]);
        }
    }
    __syncthreads();
#pragma unroll 1
    for (int ks = 0; ks < NK; ks++) {
        int cur = ks & 1, nxt = cur ^ 1;
        float4 areg = make_float4(0.f, 0.f, 0.f, 0.f);
        float breg[4] = {0.f, 0.f, 0.f, 0.f};
        if (ks + 1 < NK) {
            int k = (ks + 1) * 8 + ah * 4;
            if (k + 3 < EE) areg = *(const float4*)(arow + k);
            else {
                if (k + 0 < EE) areg.x = arow[k + 0];
                if (k + 1 < EE) areg.y = arow[k + 1];
                if (k + 2 < EE) areg.z = arow[k + 2];
                if (k + 3 < EE) areg.w = arow[k + 3];
            }
#pragma unroll
            for (int i = 0; i < 4; i++) {
                int e = tid + i * 256, kk = e >> 7, n = e & 127;
                int gk = (ks + 1) * 8 + kk;
                breg[i] = (gk < EE) ? g_wt[(size_t)gk * NW + n0 + n] : 0.f;
            }
        }
        mm_inner(As[cur], Bsu[cur], tx, ty, acc);
        if (ks + 1 < NK) {
            *(float4*)&As[nxt][am][ah * 4] = areg;
#pragma unroll
            for (int i = 0; i < 4; i++) {
                int e = tid + i * 256, kk = e >> 7, n = e & 127;
                bs_put(Bsu[nxt], kk, n, breg[i]);
            }
            __syncthreads();
        }
    }
#pragma unroll
    for (int r = 0; r < 16; r++) {
        int row = m0 + ty * 16 + r;
#pragma unroll
        for (int c = 0; c < 4; c++) {
            float lo, hi;
            f2unpack(acc[r][c], lo, hi);
            float v = lo + hi;
            int col = n0 + tx + 32 * c;
            if (col < G3) g_gx_f[(size_t)row * G3 + col] = v + bihf[col];
            else          g_gx_b[(size_t)row * G3 + col - G3] = v + bihb[col - G3];
        }
    }
}

// ---------------- GRU: 32 persistent CTAs (dir x batch) ----------------------
__global__ __launch_bounds__(384, 1) void gru_kernel(const float* __restrict__ whhf,
                                                     const float* __restrict__ whhb,
                                                     const float* __restrict__ bhhf,
                                                     const float* __restrict__ bhhb) {
    const int dir = blockIdx.x >> 4;
    const int b = blockIdx.x & 15;
    const int j = threadIdx.x;
    const float* whh = dir ? whhb : whhf;
    const float* bhh = dir ? bhhb : bhhf;
    const float* gx = dir ? g_gx_b : g_gx_f;

    __shared__ __align__(16) float hs[HH];
    __shared__ float ghs[G3];

    ull w[64];
    const ull* wr = (const ull*)(whh + (size_t)j * HH);
#pragma unroll
    for (int i = 0; i < 64; i++) w[i] = wr[i];
    const float bj = bhh[j];

    if (j < HH) hs[j] = 0.f;
    __syncthreads();

    for (int t = 0; t < SS; t++) {
        const int s = dir ? (SS - 1 - t) : t;
        const float* grow = gx + ((size_t)b * SS + s) * G3;
        // gh[j] = h . whh[j,:]  via 4 independent f32x2 chains (broadcast hs reads)
        ull a0 = 0, a1 = 0, a2 = 0, a3 = 0;
        const ulonglong2* hp = (const ulonglong2*)hs;
#pragma unroll
        for (int i = 0; i < 16; i++) {
            ulonglong2 h0 = hp[2 * i], h1 = hp[2 * i + 1];
            ffma2(a0, w[4 * i + 0], h0.x);
            ffma2(a1, w[4 * i + 1], h0.y);
            ffma2(a2, w[4 * i + 2], h1.x);
            ffma2(a3, w[4 * i + 3], h1.y);
        }
        float l0, h0f, l1, h1f, l2, h2f, l3, h3f;
        f2unpack(a0, l0, h0f); f2unpack(a1, l1, h1f);
        f2unpack(a2, l2, h2f); f2unpack(a3, l3, h3f);
        ghs[j] = (l0 + h0f) + (l1 + h1f) + (l2 + h2f) + (l3 + h3f) + bj;
        __syncthreads();
        if (j < HH) {
            float xr = grow[j], xz = grow[HH + j], xn = grow[2 * HH + j];
            float r = sigmf(xr + ghs[j]);
            float z = sigmf(xz + ghs[HH + j]);
            float n = tanhf(xn + r * ghs[2 * HH + j]);
            float hnew = (1.f - z) * n + z * hs[j];
            hs[j] = hnew;
            g_rh[((size_t)b * SS + s) * H2D + dir * HH + j] = hnew;
        }
        __syncthreads();
    }
}

// ---------------- GEMM2: q[b,h,s,:] = rh[b,s,:] @ W_m[h] ---------------------
__global__ __launch_bounds__(256) void gemm2_kernel(const float* __restrict__ wm) {
    __shared__ __align__(16) float As[2][128][8];
    __shared__ __align__(16) ull Bsu[2][4][128];
    const int tid = threadIdx.x;
    const int m0 = blockIdx.y * 128, n0 = blockIdx.x * 128, h = blockIdx.z;
    const int tx = tid & 31, ty = tid >> 5;
    const int am = tid >> 1, ah = tid & 1;
    const float* Aglob = g_rh + ((size_t)m0 + am) * H2D;
    const float* Bglob = wm + (size_t)h * H2D * H2D;

    ull acc[16][4];
#pragma unroll
    for (int r = 0; r < 16; r++)
#pragma unroll
        for (int c = 0; c < 4; c++) acc[r][c] = 0ull;

    const int NK = H2D / 8;  // 32
    {
        *(float4*)&As[0][am][ah * 4] = *(const float4*)(Aglob + ah * 4);
#pragma unroll
        for (int i = 0; i < 4; i++) {
            int e = tid + i * 256, kk = e >> 7, n = e & 127;
            bs_put(Bsu[0], kk, n, Bglob[(size_t)kk * H2D + n0 + n]);
        }
    }
    __syncthreads();
#pragma unroll 1
    for (int ks = 0; ks < NK; ks++) {
        int cur = ks & 1, nxt = cur ^ 1;
        float4 areg;
        float breg[4];
        if (ks + 1 < NK) {
            int k = (ks + 1) * 8;
            areg = *(const float4*)(Aglob + k + ah * 4);
#pragma unroll
            for (int i = 0; i < 4; i++) {
                int e = tid + i * 256, kk = e >> 7, n = e & 127;
                breg[i] = Bglob[(size_t)(k + kk) * H2D + n0 + n];
            }
        }
        mm_inner(As[cur], Bsu[cur], tx, ty, acc);
        if (ks + 1 < NK) {
            *(float4*)&As[nxt][am][ah * 4] = areg;
#pragma unroll
            for (int i = 0; i < 4; i++) {
                int e = tid + i * 256, kk = e >> 7, n = e & 127;
                bs_put(Bsu[nxt], kk, n, breg[i]);
            }
            __syncthreads();
        }
    }
#pragma unroll
    for (int r = 0; r < 16; r++) {
        int m = m0 + ty * 16 + r;
        int b = m >> 10, s = m & 1023;
        float* qrow = g_q + (((size_t)b * NHEAD + h) * SS + s) * H2D;
#pragma unroll
        for (int c = 0; c < 4; c++) {
            float lo, hi;
            f2unpack(acc[r][c], lo, hi);
            qrow[n0 + tx + 32 * c] = lo + hi;
        }
    }
}

// ---------------- vproj: vp[b,t,o] = rh[b,t,:] . wr[o,:]; key bias -----------
__global__ __launch_bounds__(256) void vproj_kernel(const float* __restrict__ wrw,
                                                    const float* __restrict__ mask) {
    __shared__ float wsh[3][H2D];
    int tid = threadIdx.x;
    wsh[0][tid] = wrw[tid];
    wsh[1][tid] = wrw[H2D + tid];
    wsh[2][tid] = wrw[2 * H2D + tid];
    __syncthreads();
    int gw = (blockIdx.x * 256 + tid) >> 5;
    int lane = tid & 31;
    for (int r = gw; r < BB * SS; r += 2048) {
        const float* rp = g_rh + (size_t)r * H2D;
        float s0 = 0.f, s1 = 0.f, s2 = 0.f;
#pragma unroll
        for (int i = 0; i < 8; i++) {
            float v = rp[lane + i * 32];
            s0 += v * wsh[0][lane + i * 32];
            s1 += v * wsh[1][lane + i * 32];
            s2 += v * wsh[2][lane + i * 32];
        }
#pragma unroll
        for (int off = 16; off; off >>= 1) {
            s0 += __shfl_down_sync(0xffffffffu, s0, off);
            s1 += __shfl_down_sync(0xffffffffu, s1, off);
            s2 += __shfl_down_sync(0xffffffffu, s2, off);
        }
        if (lane == 0) {
            g_vp0[r] = s0;
            g_vp1[r] = s1;
            g_vp2[r] = s2;
            g_bias[r] = (mask[r] - 1.f) * 1e11f;
        }
    }
}

// ---------------- scores: alpha[b,h,s,t] = q[b,h,s,:] . rh[b,t,:] + bias -----
__global__ __launch_bounds__(256) void scores_kernel() {
    __shared__ __align__(16) float As[2][128][8];
    __shared__ __align__(16) ull Bsu[2][4][128];
    __shared__ float biass[128];
    const int tid = threadIdx.x;
    const int bh = blockIdx.z, b = bh >> 2;
    const int m0 = blockIdx.y * 128, n0 = blockIdx.x * 128;
    const int tx = tid & 31, ty = tid >> 5;
    const int am = tid >> 1, ah = tid & 1;
    const float* Aglob = g_q + ((size_t)bh * SS + m0 + am) * H2D;
    const float* Bglob = g_rh + ((size_t)b * SS + n0 + am) * H2D;

    ull acc[16][4];
#pragma unroll
    for (int r = 0; r < 16; r++)
#pragma unroll
        for (int c = 0; c < 4; c++) acc[r][c] = 0ull;

    const int NK = H2D / 8;  // 32
    {
        float4 av = *(const float4*)(Aglob + ah * 4);
        float4 bv = *(const float4*)(Bglob + ah * 4);
        *(float4*)&As[0][am][ah * 4] = av;
        // B tile: row am is key t=n0+am, ah selects k-quad -> kp rows ah*2, ah*2+1
        Bsu[0][ah * 2 + 0][am] = f2pack(bv.x, bv.y);
        Bsu[0][ah * 2 + 1][am] = f2pack(bv.z, bv.w);
        if (tid < 128) biass[tid] = g_bias[b * SS + n0 + tid];
    }
    __syncthreads();
#pragma unroll 1
    for (int ks = 0; ks < NK; ks++) {
        int cur = ks & 1, nxt = cur ^ 1;
        float4 areg, breg;
        if (ks + 1 < NK) {
            int k = (ks + 1) * 8 + ah * 4;
            areg = *(const float4*)(Aglob + k);
            breg = *(const float4*)(Bglob + k);
        }
        mm_inner(As[cur], Bsu[cur], tx, ty, acc);
        if (ks + 1 < NK) {
            *(float4*)&As[nxt][am][ah * 4] = areg;
            Bsu[nxt][ah * 2 + 0][am] = f2pack(breg.x, breg.y);
            Bsu[nxt][ah * 2 + 1][am] = f2pack(breg.z, breg.w);
            __syncthreads();
        }
    }
    float bv0 = biass[tx], bv1 = biass[tx + 32], bv2 = biass[tx + 64], bv3 = biass[tx + 96];
#pragma unroll
    for (int r = 0; r < 16; r++) {
        int s = m0 + ty * 16 + r;
        float* crow = g_alpha + ((size_t)bh * SS + s) * SS;
        float lo, hi;
        f2unpack(acc[r][0], lo, hi); crow[n0 + tx]      = lo + hi + bv0;
        f2unpack(acc[r][1], lo, hi); crow[n0 + tx + 32] = lo + hi + bv1;
        f2unpack(acc[r][2], lo, hi); crow[n0 + tx + 64] = lo + hi + bv2;
        f2unpack(acc[r][3], lo, hi); crow[n0 + tx + 96] = lo + hi + bv3;
    }
}

// ---------------- softmax + PV(d=3) + head mix + log_softmax -----------------
__global__ __launch_bounds__(128) void smx_kernel(const float* __restrict__ wtw,
                                                  const float* __restrict__ mask,
                                                  float* __restrict__ out) {
    const int bs = blockIdx.x;           // b*S + s
    const int b = bs >> 10;
    const int tid = threadIdx.x, lane = tid & 31, h = tid >> 5;
    __shared__ float v0s[SS], v1s[SS], v2s[SS];
    __shared__ float res[NHEAD][NOUT];
    for (int i = tid; i < SS; i += 128) {
        v0s[i] = g_vp0[b * SS + i];
        v1s[i] = g_vp1[b * SS + i];
        v2s[i] = g_vp2[b * SS + i];
    }
    __syncthreads();

    const float4* arow = (const float4*)(g_alpha + (((size_t)b * NHEAD + h) * SS + (bs & 1023)) * SS);
    float m = -1e30f, d = 0.f, a0 = 0.f, a1 = 0.f, a2 = 0.f;
#pragma unroll 1
    for (int g = 0; g < 8; g++) {
        int idx = g * 32 + lane;
        float4 sc = arow[idx];
        float mx = fmaxf(fmaxf(sc.x, sc.y), fmaxf(sc.z, sc.w));
        float mn = fmaxf(m, mx);
        float scale = __expf(m - mn);
        float e0 = __expf(sc.x - mn), e1 = __expf(sc.y - mn);
        float e2 = __expf(sc.z - mn), e3 = __expf(sc.w - mn);
        d = d * scale + (e0 + e1) + (e2 + e3);
        int t = idx * 4;
        a0 = a0 * scale + e0 * v0s[t] + e1 * v0s[t + 1] + e2 * v0s[t + 2] + e3 * v0s[t + 3];
        a1 = a1 * scale + e0 * v1s[t] + e1 * v1s[t + 1] + e2 * v1s[t + 2] + e3 * v1s[t + 3];
        a2 = a2 * scale + e0 * v2s[t] + e1 * v2s[t + 1] + e2 * v2s[t + 2] + e3 * v2s[t + 3];
        m = mn;
    }
#pragma unroll
    for (int off = 16; off; off >>= 1) {
        float m2 = __shfl_xor_sync(0xffffffffu, m, off);
        float d2 = __shfl_xor_sync(0xffffffffu, d, off);
        float b0 = __shfl_xor_sync(0xffffffffu, a0, off);
        float b1 = __shfl_xor_sync(0xffffffffu, a1, off);
        float b2 = __shfl_xor_sync(0xffffffffu, a2, off);
        float M = fmaxf(m, m2);
        float e1s = __expf(m - M), e2s = __expf(m2 - M);
        d = d * e1s + d2 * e2s;
        a0 = a0 * e1s + b0 * e2s;
        a1 = a1 * e1s + b1 * e2s;
        a2 = a2 * e1s + b2 * e2s;
        m = M;
    }
    if (lane == 0) {
        float inv = 1.f / d;
        res[h][0] = a0 * inv;
        res[h][1] = a1 * inv;
        res[h][2] = a2 * inv;
    }
    __syncthreads();
    if (tid == 0) {
        float o0 = g_const[0], o1 = g_const[1], o2 = g_const[2];
#pragma unroll
        for (int hh = 0; hh < NHEAD; hh++) {
            float w = wtw[hh];
            o0 += w * res[hh][0];
            o1 += w * res[hh][1];
            o2 += w * res[hh][2];
        }
        float mm = fmaxf(o0, fmaxf(o1, o2));
        float lse = mm + logf(__expf(o0 - mm) + __expf(o1 - mm) + __expf(o2 - mm));
        float mk = mask[bs];
        out[bs * 3 + 0] = (o0 - lse) * mk;
        out[bs * 3 + 1] = (o1 - lse) * mk;
        out[bs * 3 + 2] = (o2 - lse) * mk;
    }
}

// ---------------- launch ------------------------------------------------------
extern "C" void kernel_launch(void* const* d_in, const int* in_sizes, int n_in,
                              void* d_out, int out_size) {
    const void*  review = d_in[0];
    const float* mask   = (const float*)d_in[2];
    const float* emb    = (const float*)d_in[3];
    const float* w_ih_f = (const float*)d_in[4];
    const float* w_hh_f = (const float*)d_in[5];
    const float* b_ih_f = (const float*)d_in[6];
    const float* b_hh_f = (const float*)d_in[7];
    const float* w_ih_b = (const float*)d_in[8];
    const float* w_hh_b = (const float*)d_in[9];
    const float* b_ih_b = (const float*)d_in[10];
    const float* b_hh_b = (const float*)d_in[11];
    const float* wm     = (const float*)d_in[12];
    const float* wt_w   = (const float*)d_in[13];
    const float* wt_b   = (const float*)d_in[14];
    const float* wr_w   = (const float*)d_in[15];
    const float* wr_b   = (const float*)d_in[16];
    float* out = (float*)d_out;

    prep_kernel<<<900, 256>>>(w_ih_f, w_ih_b, review, wr_w, wt_b, wr_b);
    gemm1_kernel<<<dim3(6, 128), 256>>>(review, emb, b_ih_f, b_ih_b);
    gru_kernel<<<32, 384>>>(w_hh_f, w_hh_b, b_hh_f, b_hh_b);
    gemm2_kernel<<<dim3(2, 128, NHEAD), 256>>>(wm);
    vproj_kernel<<<256, 256>>>(wr_w, mask);
    scores_kernel<<<dim3(8, 8, BB * NHEAD), 256>>>();
    smx_kernel<<<BB * SS, 128>>>(wt_w, mask, out);
}

// round 14
// speedup vs baseline: 1.0638x; 1.0638x over previous
#include <cuda_runtime.h>
#include <math.h>
#include <stdint.h>

typedef unsigned long long ull;

// Problem constants
#define BB 16
#define SS 1024
#define EE 300
#define HH 128
#define NHEAD 4
#define H2D 256
#define G3 384
#define NW 768
#define NOUT 3

// ---------------- device scratch (static globals: allocation-free) -----------
__device__ float g_gx_f[BB * SS * G3];
__device__ float g_gx_b[BB * SS * G3];
__device__ float g_wt[EE * NW];                    // [k][n] combined input weights
__device__ float g_rh[BB * SS * H2D];              // fwd 0:128, bwd 128:256
__device__ float g_q[BB * NHEAD * SS * H2D];       // 67 MB
__device__ float g_alpha[(size_t)BB * NHEAD * SS * SS];  // 268 MB scores scratch
__device__ float g_vp0[BB * SS];
__device__ float g_vp1[BB * SS];
__device__ float g_vp2[BB * SS];
__device__ float g_bias[BB * SS];                  // additive key mask bias
__device__ float g_const[NOUT];
__device__ int   g_is64;

// ---------------- f32x2 packed helpers ---------------------------------------
__device__ __forceinline__ void ffma2(ull& c, ull a, ull b) {
    asm("fma.rn.f32x2 %0, %1, %2, %0;" : "+l"(c) : "l"(a), "l"(b));
}
__device__ __forceinline__ ull f2pack(float lo, float hi) {
    ull u;
    asm("mov.b64 %0, {%1,%2};" : "=l"(u) : "f"(lo), "f"(hi));
    return u;
}
__device__ __forceinline__ void f2unpack(ull u, float& lo, float& hi) {
    asm("mov.b64 {%0,%1}, %2;" : "=f"(lo), "=f"(hi) : "l"(u));
}
__device__ __forceinline__ float sigmf(float x) { return 1.f / (1.f + expf(-x)); }

// ---------------- prep: transpose w_ih, dtype detect, consts -----------------
__global__ void prep_kernel(const float* __restrict__ wf, const float* __restrict__ wb,
                            const void* __restrict__ review,
                            const float* __restrict__ wrw, const float* __restrict__ wtb,
                            const float* __restrict__ wrb) {
    int idx = blockIdx.x * blockDim.x + threadIdx.x;
    if (idx == 0) {
        // int64 tokens -> odd 32-bit words all zero (tokens < 32000)
        const int* r = (const int*)review;
        int all0 = 1;
        for (int i = 1; i < 128; i += 2)
            if (r[i] != 0) all0 = 0;
        g_is64 = all0;
    }
    if (idx < NOUT) {
        float s = 0.f;
        for (int d = 0; d < H2D; d++) s += wrw[idx * H2D + d];
        g_const[idx] = wtb[0] * s + wrb[idx];
    }
    if (idx < EE * NW) {
        int k = idx / NW, n = idx % NW;
        g_wt[idx] = (n < G3) ? wf[n * EE + k] : wb[(n - G3) * EE + k];
    }
}

// ---------------- shared 64x128 fp32x2 microkernel (8x8 per thread) ----------
// As: [64][8] floats, k-fastest (warp-broadcast reads -> conflict-free).
// Bsu: [kp][n] ulls, ull = packed (k=2kp, k=2kp+1) for output column n.
// Thread (tx=tid&31, ty=tid>>5) owns rows ty*8..+7, cols {tx,tx+32,tx+64,tx+96}.
// acc[8][4] = 64 regs -> fits 2 CTAs/SM (4 warps/SMSP) for latency hiding.
__device__ __forceinline__ void mm_inner8(const float (*As)[8], const ull (*Bsu)[128],
                                          int tx, int ty, ull acc[8][4]) {
    const ull* ap = (const ull*)As[ty * 8];
#pragma unroll
    for (int kp = 0; kp < 4; kp++) {
        ull b0 = Bsu[kp][tx];
        ull b1 = Bsu[kp][tx + 32];
        ull b2 = Bsu[kp][tx + 64];
        ull b3 = Bsu[kp][tx + 96];
#pragma unroll
        for (int r = 0; r < 8; r++) {
            ull a = ap[r * 4 + kp];
            ffma2(acc[r][0], a, b0);
            ffma2(acc[r][1], a, b1);
            ffma2(acc[r][2], a, b2);
            ffma2(acc[r][3], a, b3);
        }
    }
}

// Store one float of B (global [k][n] layout) into the packed smem tile.
__device__ __forceinline__ void bs_put(ull (*Bsu)[128], int kk, int n, float v) {
    ((float*)&Bsu[kk >> 1][n])[kk & 1] = v;
}

// ---------------- GEMM1: gx = emb[review] @ w_ih^T + b_ih --------------------
// Tile 64x128, grid (6, 256)
__global__ __launch_bounds__(256, 2) void gemm1_kernel(const void* __restrict__ review,
                                                       const float* __restrict__ emb,
                                                       const float* __restrict__ bihf,
                                                       const float* __restrict__ bihb) {
    __shared__ __align__(16) float As[2][64][8];
    __shared__ __align__(16) ull Bsu[2][4][128];
    const int tid = threadIdx.x;
    const int m0 = blockIdx.y * 64, n0 = blockIdx.x * 128;
    const int tx = tid & 31, ty = tid >> 5;
    const int arow = tid >> 1, ah = tid & 1;      // A loaders: tid < 128
    const bool al = tid < 128;
    const float* arowp = nullptr;
    if (al) {
        const int is64 = g_is64;
        int tok = is64 ? (int)((const long long*)review)[m0 + arow]
                       : ((const int*)review)[m0 + arow];
        arowp = emb + (size_t)tok * EE;
    }

    ull acc[8][4];
#pragma unroll
    for (int r = 0; r < 8; r++)
#pragma unroll
        for (int c = 0; c < 4; c++) acc[r][c] = 0ull;

    const int NK = (EE + 7) / 8;  // 38
    {   // preload tile 0
        if (al) *(float4*)&As[0][arow][ah * 4] = *(const float4*)(arowp + ah * 4);
#pragma unroll
        for (int i = 0; i < 4; i++) {
            int e = tid + i * 256, kk = e >> 7, n = e & 127;
            bs_put(Bsu[0], kk, n, g_wt[(size_t)kk * NW + n0 + n]);
        }
    }
    __syncthreads();
#pragma unroll 1
    for (int ks = 0; ks < NK; ks++) {
        int cur = ks & 1, nxt = cur ^ 1;
        float4 areg = make_float4(0.f, 0.f, 0.f, 0.f);
        float breg[4] = {0.f, 0.f, 0.f, 0.f};
        if (ks + 1 < NK) {
            if (al) {
                int k = (ks + 1) * 8 + ah * 4;
                if (k + 3 < EE) areg = *(const float4*)(arowp + k);
                else {
                    if (k + 0 < EE) areg.x = arowp[k + 0];
                    if (k + 1 < EE) areg.y = arowp[k + 1];
                    if (k + 2 < EE) areg.z = arowp[k + 2];
                    if (k + 3 < EE) areg.w = arowp[k + 3];
                }
            }
#pragma unroll
            for (int i = 0; i < 4; i++) {
                int e = tid + i * 256, kk = e >> 7, n = e & 127;
                int gk = (ks + 1) * 8 + kk;
                breg[i] = (gk < EE) ? g_wt[(size_t)gk * NW + n0 + n] : 0.f;
            }
        }
        mm_inner8(As[cur], Bsu[cur], tx, ty, acc);
        if (ks + 1 < NK) {
            if (al) *(float4*)&As[nxt][arow][ah * 4] = areg;
#pragma unroll
            for (int i = 0; i < 4; i++) {
                int e = tid + i * 256, kk = e >> 7, n = e & 127;
                bs_put(Bsu[nxt], kk, n, breg[i]);
            }
            __syncthreads();
        }
    }
#pragma unroll
    for (int r = 0; r < 8; r++) {
        int row = m0 + ty * 8 + r;
#pragma unroll
        for (int c = 0; c < 4; c++) {
            float lo, hi;
            f2unpack(acc[r][c], lo, hi);
            float v = lo + hi;
            int col = n0 + tx + 32 * c;
            if (col < G3) g_gx_f[(size_t)row * G3 + col] = v + bihf[col];
            else          g_gx_b[(size_t)row * G3 + col - G3] = v + bihb[col - G3];
        }
    }
}

// ---------------- GRU: 32 persistent CTAs (dir x batch), gx prefetch --------
__global__ __launch_bounds__(384, 1) void gru_kernel(const float* __restrict__ whhf,
                                                     const float* __restrict__ whhb,
                                                     const float* __restrict__ bhhf,
                                                     const float* __restrict__ bhhb) {
    const int dir = blockIdx.x >> 4;
    const int b = blockIdx.x & 15;
    const int j = threadIdx.x;
    const float* whh = dir ? whhb : whhf;
    const float* bhh = dir ? bhhb : bhhf;
    const float* gx = dir ? g_gx_b : g_gx_f;

    __shared__ __align__(16) float hs[HH];
    __shared__ float ghs[G3];

    ull w[64];
    const ull* wr = (const ull*)(whh + (size_t)j * HH);
#pragma unroll
    for (int i = 0; i < 64; i++) w[i] = wr[i];
    const float bj = bhh[j];

    if (j < HH) hs[j] = 0.f;

    // preload gate inputs for t=0 (off the recurrence critical path)
    float xr = 0.f, xz = 0.f, xn = 0.f;
    if (j < HH) {
        int s0 = dir ? (SS - 1) : 0;
        const float* g0 = gx + ((size_t)b * SS + s0) * G3;
        xr = g0[j]; xz = g0[HH + j]; xn = g0[2 * HH + j];
    }
    __syncthreads();

    for (int t = 0; t < SS; t++) {
        const int s = dir ? (SS - 1 - t) : t;
        // prefetch next step's gate inputs (independent of h -> hides LDG latency)
        float nxr = 0.f, nxz = 0.f, nxn = 0.f;
        if (t + 1 < SS && j < HH) {
            int s2 = dir ? (SS - 2 - t) : (t + 1);
            const float* g2 = gx + ((size_t)b * SS + s2) * G3;
            nxr = g2[j]; nxz = g2[HH + j]; nxn = g2[2 * HH + j];
        }
        // gh[j] = h . whh[j,:]  via 4 independent f32x2 chains (broadcast hs reads)
        ull a0 = 0, a1 = 0, a2 = 0, a3 = 0;
        const ulonglong2* hp = (const ulonglong2*)hs;
#pragma unroll
        for (int i = 0; i < 16; i++) {
            ulonglong2 h0 = hp[2 * i], h1 = hp[2 * i + 1];
            ffma2(a0, w[4 * i + 0], h0.x);
            ffma2(a1, w[4 * i + 1], h0.y);
            ffma2(a2, w[4 * i + 2], h1.x);
            ffma2(a3, w[4 * i + 3], h1.y);
        }
        float l0, h0f, l1, h1f, l2, h2f, l3, h3f;
        f2unpack(a0, l0, h0f); f2unpack(a1, l1, h1f);
        f2unpack(a2, l2, h2f); f2unpack(a3, l3, h3f);
        ghs[j] = (l0 + h0f) + (l1 + h1f) + (l2 + h2f) + (l3 + h3f) + bj;
        __syncthreads();
        if (j < HH) {
            float r = sigmf(xr + ghs[j]);
            float z = sigmf(xz + ghs[HH + j]);
            float n = tanhf(xn + r * ghs[2 * HH + j]);
            float hnew = (1.f - z) * n + z * hs[j];
            hs[j] = hnew;
            g_rh[((size_t)b * SS + s) * H2D + dir * HH + j] = hnew;
            xr = nxr; xz = nxz; xn = nxn;
        }
        __syncthreads();
    }
}

// ---------------- GEMM2: q[b,h,s,:] = rh[b,s,:] @ W_m[h] ---------------------
// Tile 64x128, grid (2, 256, NHEAD)
__global__ __launch_bounds__(256, 2) void gemm2_kernel(const float* __restrict__ wm) {
    __shared__ __align__(16) float As[2][64][8];
    __shared__ __align__(16) ull Bsu[2][4][128];
    const int tid = threadIdx.x;
    const int m0 = blockIdx.y * 64, n0 = blockIdx.x * 128, h = blockIdx.z;
    const int tx = tid & 31, ty = tid >> 5;
    const int arow = tid >> 1, ah = tid & 1;
    const bool al = tid < 128;
    const float* Aglob = g_rh + ((size_t)m0 + arow) * H2D;
    const float* Bglob = wm + (size_t)h * H2D * H2D;

    ull acc[8][4];
#pragma unroll
    for (int r = 0; r < 8; r++)
#pragma unroll
        for (int c = 0; c < 4; c++) acc[r][c] = 0ull;

    const int NK = H2D / 8;  // 32
    {
        if (al) *(float4*)&As[0][arow][ah * 4] = *(const float4*)(Aglob + ah * 4);
#pragma unroll
        for (int i = 0; i < 4; i++) {
            int e = tid + i * 256, kk = e >> 7, n = e & 127;
            bs_put(Bsu[0], kk, n, Bglob[(size_t)kk * H2D + n0 + n]);
        }
    }
    __syncthreads();
#pragma unroll 1
    for (int ks = 0; ks < NK; ks++) {
        int cur = ks & 1, nxt = cur ^ 1;
        float4 areg = make_float4(0.f, 0.f, 0.f, 0.f);
        float breg[4];
        if (ks + 1 < NK) {
            int k = (ks + 1) * 8;
            if (al) areg = *(const float4*)(Aglob + k + ah * 4);
#pragma unroll
            for (int i = 0; i < 4; i++) {
                int e = tid + i * 256, kk = e >> 7, n = e & 127;
                breg[i] = Bglob[(size_t)(k + kk) * H2D + n0 + n];
            }
        }
        mm_inner8(As[cur], Bsu[cur], tx, ty, acc);
        if (ks + 1 < NK) {
            if (al) *(float4*)&As[nxt][arow][ah * 4] = areg;
#pragma unroll
            for (int i = 0; i < 4; i++) {
                int e = tid + i * 256, kk = e >> 7, n = e & 127;
                bs_put(Bsu[nxt], kk, n, breg[i]);
            }
            __syncthreads();
        }
    }
#pragma unroll
    for (int r = 0; r < 8; r++) {
        int m = m0 + ty * 8 + r;
        int b = m >> 10, s = m & 1023;
        float* qrow = g_q + (((size_t)b * NHEAD + h) * SS + s) * H2D;
#pragma unroll
        for (int c = 0; c < 4; c++) {
            float lo, hi;
            f2unpack(acc[r][c], lo, hi);
            qrow[n0 + tx + 32 * c] = lo + hi;
        }
    }
}

// ---------------- vproj: vp[b,t,o] = rh[b,t,:] . wr[o,:]; key bias -----------
__global__ __launch_bounds__(256) void vproj_kernel(const float* __restrict__ wrw,
                                                    const float* __restrict__ mask) {
    __shared__ float wsh[3][H2D];
    int tid = threadIdx.x;
    wsh[0][tid] = wrw[tid];
    wsh[1][tid] = wrw[H2D + tid];
    wsh[2][tid] = wrw[2 * H2D + tid];
    __syncthreads();
    int gw = (blockIdx.x * 256 + tid) >> 5;
    int lane = tid & 31;
    for (int r = gw; r < BB * SS; r += 2048) {
        const float* rp = g_rh + (size_t)r * H2D;
        float s0 = 0.f, s1 = 0.f, s2 = 0.f;
#pragma unroll
        for (int i = 0; i < 8; i++) {
            float v = rp[lane + i * 32];
            s0 += v * wsh[0][lane + i * 32];
            s1 += v * wsh[1][lane + i * 32];
            s2 += v * wsh[2][lane + i * 32];
        }
#pragma unroll
        for (int off = 16; off; off >>= 1) {
            s0 += __shfl_down_sync(0xffffffffu, s0, off);
            s1 += __shfl_down_sync(0xffffffffu, s1, off);
            s2 += __shfl_down_sync(0xffffffffu, s2, off);
        }
        if (lane == 0) {
            g_vp0[r] = s0;
            g_vp1[r] = s1;
            g_vp2[r] = s2;
            g_bias[r] = (mask[r] - 1.f) * 1e11f;
        }
    }
}

// ---------------- scores: alpha[b,h,s,t] = q[b,h,s,:] . rh[b,t,:] + bias -----
// Tile 64x128, grid (8, 16, 64)
__global__ __launch_bounds__(256, 2) void scores_kernel() {
    __shared__ __align__(16) float As[2][64][8];
    __shared__ __align__(16) ull Bsu[2][4][128];
    __shared__ float biass[128];
    const int tid = threadIdx.x;
    const int bh = blockIdx.z, b = bh >> 2;
    const int m0 = blockIdx.y * 64, n0 = blockIdx.x * 128;
    const int tx = tid & 31, ty = tid >> 5;
    const int arow = tid >> 1, ah = tid & 1;      // arow: A row (tid<128) or B key row (all)
    const int am = tid >> 1;
    const bool al = tid < 128;
    const float* Aglob = g_q + ((size_t)bh * SS + m0 + arow) * H2D;
    const float* Bglob = g_rh + ((size_t)b * SS + n0 + am) * H2D;

    ull acc[8][4];
#pragma unroll
    for (int r = 0; r < 8; r++)
#pragma unroll
        for (int c = 0; c < 4; c++) acc[r][c] = 0ull;

    const int NK = H2D / 8;  // 32
    {
        if (al) *(float4*)&As[0][arow][ah * 4] = *(const float4*)(Aglob + ah * 4);
        float4 bv = *(const float4*)(Bglob + ah * 4);
        // B tile: row am is key t=n0+am, ah selects k-quad -> kp rows ah*2, ah*2+1
        Bsu[0][ah * 2 + 0][am] = f2pack(bv.x, bv.y);
        Bsu[0][ah * 2 + 1][am] = f2pack(bv.z, bv.w);
        if (tid < 128) biass[tid] = g_bias[b * SS + n0 + tid];
    }
    __syncthreads();
#pragma unroll 1
    for (int ks = 0; ks < NK; ks++) {
        int cur = ks & 1, nxt = cur ^ 1;
        float4 areg = make_float4(0.f, 0.f, 0.f, 0.f);
        float4 breg;
        if (ks + 1 < NK) {
            int k = (ks + 1) * 8 + ah * 4;
            if (al) areg = *(const float4*)(Aglob + k);
            breg = *(const float4*)(Bglob + k);
        }
        mm_inner8(As[cur], Bsu[cur], tx, ty, acc);
        if (ks + 1 < NK) {
            if (al) *(float4*)&As[nxt][arow][ah * 4] = areg;
            Bsu[nxt][ah * 2 + 0][am] = f2pack(breg.x, breg.y);
            Bsu[nxt][ah * 2 + 1][am] = f2pack(breg.z, breg.w);
            __syncthreads();
        }
    }
    float bv0 = biass[tx], bv1 = biass[tx + 32], bv2 = biass[tx + 64], bv3 = biass[tx + 96];
#pragma unroll
    for (int r = 0; r < 8; r++) {
        int s = m0 + ty * 8 + r;
        float* crow = g_alpha + ((size_t)bh * SS + s) * SS;
        float lo, hi;
        f2unpack(acc[r][0], lo, hi); crow[n0 + tx]      = lo + hi + bv0;
        f2unpack(acc[r][1], lo, hi); crow[n0 + tx + 32] = lo + hi + bv1;
        f2unpack(acc[r][2], lo, hi); crow[n0 + tx + 64] = lo + hi + bv2;
        f2unpack(acc[r][3], lo, hi); crow[n0 + tx + 96] = lo + hi + bv3;
    }
}

// ---------------- softmax + PV(d=3) + head mix + log_softmax -----------------
__global__ __launch_bounds__(128) void smx_kernel(const float* __restrict__ wtw,
                                                  const float* __restrict__ mask,
                                                  float* __restrict__ out) {
    const int bs = blockIdx.x;           // b*S + s
    const int b = bs >> 10;
    const int tid = threadIdx.x, lane = tid & 31, h = tid >> 5;
    __shared__ float v0s[SS], v1s[SS], v2s[SS];
    __shared__ float res[NHEAD][NOUT];
    for (int i = tid; i < SS; i += 128) {
        v0s[i] = g_vp0[b * SS + i];
        v1s[i] = g_vp1[b * SS + i];
        v2s[i] = g_vp2[b * SS + i];
    }
    __syncthreads();

    const float4* arow = (const float4*)(g_alpha + (((size_t)b * NHEAD + h) * SS + (bs & 1023)) * SS);
    float m = -1e30f, d = 0.f, a0 = 0.f, a1 = 0.f, a2 = 0.f;
#pragma unroll 1
    for (int g = 0; g < 8; g++) {
        int idx = g * 32 + lane;
        float4 sc = arow[idx];
        float mx = fmaxf(fmaxf(sc.x, sc.y), fmaxf(sc.z, sc.w));
        float mn = fmaxf(m, mx);
        float scale = __expf(m - mn);
        float e0 = __expf(sc.x - mn), e1 = __expf(sc.y - mn);
        float e2 = __expf(sc.z - mn), e3 = __expf(sc.w - mn);
        d = d * scale + (e0 + e1) + (e2 + e3);
        int t = idx * 4;
        a0 = a0 * scale + e0 * v0s[t] + e1 * v0s[t + 1] + e2 * v0s[t + 2] + e3 * v0s[t + 3];
        a1 = a1 * scale + e0 * v1s[t] + e1 * v1s[t + 1] + e2 * v1s[t + 2] + e3 * v1s[t + 3];
        a2 = a2 * scale + e0 * v2s[t] + e1 * v2s[t + 1] + e2 * v2s[t + 2] + e3 * v2s[t + 3];
        m = mn;
    }
#pragma unroll
    for (int off = 16; off; off >>= 1) {
        float m2 = __shfl_xor_sync(0xffffffffu, m, off);
        float d2 = __shfl_xor_sync(0xffffffffu, d, off);
        float b0 = __shfl_xor_sync(0xffffffffu, a0, off);
        float b1 = __shfl_xor_sync(0xffffffffu, a1, off);
        float b2 = __shfl_xor_sync(0xffffffffu, a2, off);
        float M = fmaxf(m, m2);
        float e1s = __expf(m - M), e2s = __expf(m2 - M);
        d = d * e1s + d2 * e2s;
        a0 = a0 * e1s + b0 * e2s;
        a1 = a1 * e1s + b1 * e2s;
        a2 = a2 * e1s + b2 * e2s;
        m = M;
    }
    if (lane == 0) {
        float inv = 1.f / d;
        res[h][0] = a0 * inv;
        res[h][1] = a1 * inv;
        res[h][2] = a2 * inv;
    }
    __syncthreads();
    if (tid == 0) {
        float o0 = g_const[0], o1 = g_const[1], o2 = g_const[2];
#pragma unroll
        for (int hh = 0; hh < NHEAD; hh++) {
            float w = wtw[hh];
            o0 += w * res[hh][0];
            o1 += w * res[hh][1];
            o2 += w * res[hh][2];
        }
        float mm = fmaxf(o0, fmaxf(o1, o2));
        float lse = mm + logf(__expf(o0 - mm) + __expf(o1 - mm) + __expf(o2 - mm));
        float mk = mask[bs];
        out[bs * 3 + 0] = (o0 - lse) * mk;
        out[bs * 3 + 1] = (o1 - lse) * mk;
        out[bs * 3 + 2] = (o2 - lse) * mk;
    }
}

// ---------------- launch ------------------------------------------------------
extern "C" void kernel_launch(void* const* d_in, const int* in_sizes, int n_in,
                              void* d_out, int out_size) {
    const void*  review = d_in[0];
    const float* mask   = (const float*)d_in[2];
    const float* emb    = (const float*)d_in[3];
    const float* w_ih_f = (const float*)d_in[4];
    const float* w_hh_f = (const float*)d_in[5];
    const float* b_ih_f = (const float*)d_in[6];
    const float* b_hh_f = (const float*)d_in[7];
    const float* w_ih_b = (const float*)d_in[8];
    const float* w_hh_b = (const float*)d_in[9];
    const float* b_ih_b = (const float*)d_in[10];
    const float* b_hh_b = (const float*)d_in[11];
    const float* wm     = (const float*)d_in[12];
    const float* wt_w   = (const float*)d_in[13];
    const float* wt_b   = (const float*)d_in[14];
    const float* wr_w   = (const float*)d_in[15];
    const float* wr_b   = (const float*)d_in[16];
    float* out = (float*)d_out;

    prep_kernel<<<900, 256>>>(w_ih_f, w_ih_b, review, wr_w, wt_b, wr_b);
    gemm1_kernel<<<dim3(6, 256), 256>>>(review, emb, b_ih_f, b_ih_b);
    gru_kernel<<<32, 384>>>(w_hh_f, w_hh_b, b_hh_f, b_hh_b);
    gemm2_kernel<<<dim3(2, 256, NHEAD), 256>>>(wm);
    vproj_kernel<<<256, 256>>>(wr_w, mask);
    scores_kernel<<<dim3(8, 16, BB * NHEAD), 256>>>();
    smx_kernel<<<BB * SS, 128>>>(wt_w, mask, out);
}